// round 2
// baseline (speedup 1.0000x reference)
#include <cuda_runtime.h>
#include <math.h>

// Problem constants (fixed shapes from reference)
#define BATCH 2048
#define TSTEPS 1000
#define NI 40          // inputs
#define NH 16          // hidden neurons
#define NR 32          // H * BRANCH rows
#define NO 2           // output classes

#define OUT_LOSS 0
#define OUT_D2   1
#define OUT_CORR (1 + (size_t)BATCH * TSTEPS * NO)
#define OUT_TOT  (OUT_CORR + 1)

__global__ void init_out(float* out) {
    if (threadIdx.x == 0 && blockIdx.x == 0) {
        out[OUT_LOSS] = 0.0f;
        int c = 0;
        for (int t = 0; t < TSTEPS; ++t)
            if (t > 10 && ((t - 10) % 15) > 5) c++;
        out[OUT_CORR] = 0.0f;
        out[OUT_TOT] = (float)c * (float)BATCH;
    }
}

__global__ __launch_bounds__(32) void snn_kernel(
    const float* __restrict__ x,       // [B, T, NI]
    const int*   __restrict__ target,  // [B, T]
    const float* __restrict__ W1,      // [NR, NI]
    const float* __restrict__ tau_m,   // [NH]
    const float* __restrict__ tau_n,   // [NH, 2] == [NR]
    const float* __restrict__ mask,    // [NR, NI]
    const float* __restrict__ W2,      // [NO, NH]
    const float* __restrict__ b2,      // [NO]
    float*       __restrict__ out)
{
    const int b    = blockIdx.x;       // one warp (block) per batch element
    const int lane = threadIdx.x;      // lane = neuron*2 + branch
    const int h    = lane >> 1;

    // Masked dendritic weight row lives in registers (exactly 40 regs).
    float w[NI];
    #pragma unroll
    for (int k = 0; k < NI; ++k)
        w[k] = W1[lane * NI + k] * mask[lane * NI + k];

    const float beta    = 1.0f / (1.0f + expf(-tau_n[lane]));   // dendritic decay
    const float ombeta  = 1.0f - beta;
    const float alpha   = 1.0f / (1.0f + expf(-tau_m[h]));      // membrane decay
    const float omalpha = 1.0f - alpha;
    // even lane contributes spk*W2[0][h], odd lane spk*W2[1][h]
    const float w2sel = (lane & 1) ? W2[NH + h] : W2[h];
    const float b20 = b2[0], b21 = b2[1];

    float d = 0.0f, mem = 0.0f, spk = 0.0f;
    float lossAcc = 0.0f;
    int   corrAcc = 0;

    const float* xp = x + (size_t)b * TSTEPS * NI;
    const int*   tp = target + (size_t)b * TSTEPS;
    float*       op = out + OUT_D2 + (size_t)b * TSTEPS * NO;

    const unsigned FULL = 0xffffffffu;

    for (int t = 0; t < TSTEPS; ++t) {
        // Coalesced warp load of x[b, t, 0..39]
        float xv0 = xp[lane];
        float xv1 = (lane < NI - 32) ? xp[32 + lane] : 0.0f;
        xp += NI;

        // cur[lane] = dot(w_row[lane], x_t)  — broadcast x via shfl
        float a0 = 0.0f, a1 = 0.0f;
        #pragma unroll
        for (int k = 0; k < 32; k += 2) {
            a0 = fmaf(w[k],     __shfl_sync(FULL, xv0, k),     a0);
            a1 = fmaf(w[k + 1], __shfl_sync(FULL, xv0, k + 1), a1);
        }
        #pragma unroll
        for (int k = 0; k < NI - 32; k += 2) {
            a0 = fmaf(w[32 + k],     __shfl_sync(FULL, xv1, k),     a0);
            a1 = fmaf(w[32 + k + 1], __shfl_sync(FULL, xv1, k + 1), a1);
        }
        float cur = a0 + a1;

        // dendrite update + pair-sum across the two branches of this neuron
        d = fmaf(beta, d, ombeta * cur);
        float l = d + __shfl_xor_sync(FULL, d, 1);   // identical on both pair lanes

        // membrane update with previous spike reset, then new spike
        mem = fmaf(alpha, mem - spk, omalpha * l);
        spk = (mem > 1.0f) ? 1.0f : 0.0f;            // VTH = 1

        // logits: parity-preserving xor reduction over 16 even / 16 odd lanes
        float part = spk * w2sel;
        part += __shfl_xor_sync(FULL, part, 2);
        part += __shfl_xor_sync(FULL, part, 4);
        part += __shfl_xor_sync(FULL, part, 8);
        part += __shfl_xor_sync(FULL, part, 16);
        float other = __shfl_xor_sync(FULL, part, 1);
        float l0 = ((lane & 1) ? other : part) + b20;
        float l1 = ((lane & 1) ? part : other) + b21;

        // d2_output[b, t, :]  (two lanes, one STG, same sector)
        if (lane < 2) op[t * 2 + lane] = lane ? l1 : l0;

        // CE / accuracy only on flagged timesteps
        bool flag = (t > 10) && (((t - 10) % 15) > 5);
        if (flag) {
            float z  = l1 - l0;
            float p1 = 1.0f / (1.0f + __expf(-z));   // softmax(logits)[1]
            float p0 = 1.0f - p1;
            // CE of log_softmax applied to already-softmaxed p (double softmax)
            float lse  = __logf(__expf(p0) + __expf(p1));
            int   tgt  = tp[t];
            float ptgt = tgt ? p1 : p0;
            lossAcc += (lse - ptgt);
            corrAcc += (((z > 0.0f) ? 1 : 0) == tgt);
        }
    }

    if (lane == 0) {
        atomicAdd(&out[OUT_LOSS], lossAcc * (1.0f / (float)BATCH));
        atomicAdd(&out[OUT_CORR], (float)corrAcc);
    }
}

extern "C" void kernel_launch(void* const* d_in, const int* in_sizes, int n_in,
                              void* d_out, int out_size) {
    const float* x      = (const float*)d_in[0];
    const int*   target = (const int*)  d_in[1];
    const float* W1     = (const float*)d_in[2];
    const float* tau_m  = (const float*)d_in[3];
    const float* tau_n  = (const float*)d_in[4];
    const float* mask   = (const float*)d_in[5];
    const float* W2     = (const float*)d_in[6];
    const float* b2     = (const float*)d_in[7];
    float* out = (float*)d_out;

    init_out<<<1, 32>>>(out);
    snn_kernel<<<BATCH, 32>>>(x, target, W1, tau_m, tau_n, mask, W2, b2, out);
}

// round 4
// speedup vs baseline: 1.6733x; 1.6733x over previous
#include <cuda_runtime.h>
#include <math.h>

#define BATCH 2048
#define TSTEPS 1000
#define NI 40
#define NH 16
#define NR 32
#define NO 2

#define OUT_LOSS 0
#define OUT_D2   1
#define OUT_CORR (1 + (size_t)BATCH * TSTEPS * NO)
#define OUT_TOT  (OUT_CORR + 1)

#define W2SCALE 16777216.0f          // 2^24
#define W2SCALE_INV 5.9604644775e-8f // 2^-24

__global__ void init_out(float* out) {
    if (threadIdx.x == 0 && blockIdx.x == 0) {
        out[OUT_LOSS] = 0.0f;
        int c = 0;
        for (int t = 0; t < TSTEPS; ++t)
            if (t > 10 && ((t - 10) % 15) > 5) c++;
        out[OUT_CORR] = 0.0f;
        out[OUT_TOT] = (float)c * (float)BATCH;
    }
}

__device__ __forceinline__ void fma2(unsigned long long& acc,
                                     unsigned long long a,
                                     unsigned long long b) {
    asm("fma.rn.f32x2 %0, %1, %2, %3;" : "=l"(acc) : "l"(a), "l"(b), "l"(acc));
}

__device__ __forceinline__ unsigned long long packf2(float lo, float hi) {
    unsigned long long r;
    asm("mov.b64 %0, {%1, %2};" : "=l"(r) : "f"(lo), "f"(hi));
    return r;
}

__device__ __forceinline__ void unpackf2(unsigned long long v, float& lo, float& hi) {
    asm("mov.b64 {%0, %1}, %2;" : "=f"(lo), "=f"(hi) : "l"(v));
}

__global__ __launch_bounds__(32) void snn_kernel(
    const float* __restrict__ x,       // [B, T, NI]
    const int*   __restrict__ target,  // [B, T]
    const float* __restrict__ W1,      // [NR, NI]
    const float* __restrict__ tau_m,   // [NH]
    const float* __restrict__ tau_n,   // [NR]
    const float* __restrict__ mask,    // [NR, NI]
    const float* __restrict__ W2,      // [NO, NH]
    const float* __restrict__ b2,      // [NO]
    float*       __restrict__ out)
{
    const int b    = blockIdx.x;
    const int lane = threadIdx.x;
    const int h    = lane >> 1;
    const unsigned FULL = 0xffffffffu;

    // x_t staging, double buffered; rows padded to 48 floats for 16B alignment
    __shared__ __align__(16) float xbuf[2][48];

    // masked weight row packed as 20 f32x2 pairs
    unsigned long long wp[NI / 2];
    #pragma unroll
    for (int j = 0; j < NI / 2; ++j) {
        float a = W1[lane * NI + 2 * j]     * mask[lane * NI + 2 * j];
        float c = W1[lane * NI + 2 * j + 1] * mask[lane * NI + 2 * j + 1];
        wp[j] = packf2(a, c);
    }

    const float beta    = 1.0f / (1.0f + expf(-tau_n[lane]));
    const float ombeta  = 1.0f - beta;
    const float alpha   = 1.0f / (1.0f + expf(-tau_m[h]));
    const float omalpha = 1.0f - alpha;
    const float w2sel   = (lane & 1) ? W2[NH + h] : W2[h];
    const int   w2q      = __float2int_rn(w2sel * W2SCALE);
    const int   w2q_even = (lane & 1) ? 0 : w2q;   // feeds l0
    const int   w2q_odd  = (lane & 1) ? w2q : 0;   // feeds l1
    const float b20 = b2[0], b21 = b2[1];
    const float mybias = lane ? b21 : b20;         // for lanes 0/1 store

    float d = 0.0f, mem = 0.0f, spkf = 0.0f;
    float lossAcc = 0.0f;
    int   corrAcc = 0;

    const float* xp = x + (size_t)b * TSTEPS * NI;
    const int*   tp = target + (size_t)b * TSTEPS;
    float*       op = out + OUT_D2 + (size_t)b * TSTEPS * NO;

    // prologue: stage x_0
    {
        xbuf[0][lane] = xp[lane];
        if (lane < NI - 32) xbuf[0][32 + lane] = xp[32 + lane];
        __syncwarp();
    }

    int ph = -10;  // (t - 10) mod 15 tracker; flag == (ph > 5)

    #pragma unroll 2
    for (int t = 0; t < TSTEPS; ++t) {
        // ---- prefetch x_{t+1} (clamped on last iter) + target ----
        const float* xn = xp + (size_t)((t + 1 < TSTEPS) ? t + 1 : t) * NI;
        float nx0 = xn[lane];
        float nx1 = (lane < NI - 32) ? xn[32 + lane] : 0.0f;
        int   tgt = tp[t];

        // ---- matvec: cur[lane] = dot(w_row, x_t), packed f32x2 FMAs ----
        const unsigned long long* xrow =
            reinterpret_cast<const unsigned long long*>(&xbuf[t & 1][0]);
        unsigned long long acc0 = 0ull, acc1 = 0ull;
        #pragma unroll
        for (int j = 0; j < 10; ++j) {
            unsigned long long xlo = xrow[2 * j];      // broadcast LDS
            unsigned long long xhi = xrow[2 * j + 1];
            fma2(acc0, wp[2 * j],     xlo);
            fma2(acc1, wp[2 * j + 1], xhi);
        }
        float a0, a1, a2, a3;
        unpackf2(acc0, a0, a1);
        unpackf2(acc1, a2, a3);
        float cur = (a0 + a1) + (a2 + a3);

        // ---- dendrite + membrane + spike ----
        d = fmaf(ombeta, cur, beta * d);
        float l = d + __shfl_xor_sync(FULL, d, 1);
        mem = fmaf(alpha, mem - spkf, omalpha * l);
        bool spkb = mem > 1.0f;   // VTH = 1
        spkf = spkb ? 1.0f : 0.0f;

        // ---- logits via two warp-wide integer reductions ----
        int s0 = __reduce_add_sync(FULL, spkb ? w2q_even : 0);
        int s1 = __reduce_add_sync(FULL, spkb ? w2q_odd  : 0);
        float l0 = fmaf((float)s0, W2SCALE_INV, b20);
        float l1 = fmaf((float)s1, W2SCALE_INV, b21);

        // d2_output[b,t,:] — scalar stores from lanes 0/1 (4B-aligned region)
        if (lane < 2) {
            float myl = fmaf((float)(lane ? s1 : s0), W2SCALE_INV, mybias);
            op[2 * t + lane] = myl;
        }

        // ---- CE / accuracy on flagged steps (uniform branch) ----
        bool flag = ph > 5;
        ph = (ph == 14) ? 0 : ph + 1;
        if (flag) {
            float z  = l1 - l0;
            float p1 = 1.0f / (1.0f + __expf(-z));
            float p0 = 1.0f - p1;
            float lse = __logf(__expf(p0) + __expf(p1)); // double softmax CE
            float ptgt = tgt ? p1 : p0;
            lossAcc += (lse - ptgt);
            corrAcc += (((z > 0.0f) ? 1 : 0) == tgt);
        }

        // ---- stage x_{t+1} into the other buffer ----
        xbuf[(t + 1) & 1][lane] = nx0;
        if (lane < NI - 32) xbuf[(t + 1) & 1][32 + lane] = nx1;
        __syncwarp();
    }

    if (lane == 0) {
        atomicAdd(&out[OUT_LOSS], lossAcc * (1.0f / (float)BATCH));
        atomicAdd(&out[OUT_CORR], (float)corrAcc);
    }
}

extern "C" void kernel_launch(void* const* d_in, const int* in_sizes, int n_in,
                              void* d_out, int out_size) {
    const float* x      = (const float*)d_in[0];
    const int*   target = (const int*)  d_in[1];
    const float* W1     = (const float*)d_in[2];
    const float* tau_m  = (const float*)d_in[3];
    const float* tau_n  = (const float*)d_in[4];
    const float* mask   = (const float*)d_in[5];
    const float* W2     = (const float*)d_in[6];
    const float* b2     = (const float*)d_in[7];
    float* out = (float*)d_out;

    init_out<<<1, 32>>>(out);
    snn_kernel<<<BATCH, 32>>>(x, target, W1, tau_m, tau_n, mask, W2, b2, out);
}

// round 5
// speedup vs baseline: 1.7464x; 1.0437x over previous
#include <cuda_runtime.h>
#include <math.h>

#define BATCH 2048
#define TSTEPS 1000
#define NI 40
#define NH 16
#define NR 32
#define NO 2

#define CHUNKS 8
#define CHLEN (TSTEPS / CHUNKS)   // 125

#define OUT_LOSS 0
#define OUT_D2   1
#define OUT_CORR (1 + (size_t)BATCH * TSTEPS * NO)
#define OUT_TOT  (OUT_CORR + 1)

#define W2SCALE 16777216.0f          // 2^24
#define W2SCALE_INV 5.9604644775e-8f // 2^-24

// 262 MB scratch: pre-scaled dendritic currents pc[b][t][r] = (1-beta_r)*cur
__device__ float g_cur[(size_t)BATCH * TSTEPS * NR];

__global__ void init_out(float* out) {
    if (threadIdx.x == 0 && blockIdx.x == 0) {
        out[OUT_LOSS] = 0.0f;
        int c = 0;
        for (int t = 0; t < TSTEPS; ++t)
            if (t > 10 && ((t - 10) % 15) > 5) c++;
        out[OUT_CORR] = 0.0f;
        out[OUT_TOT] = (float)c * (float)BATCH;
    }
}

__device__ __forceinline__ void fma2(unsigned long long& acc,
                                     unsigned long long a,
                                     unsigned long long b) {
    asm("fma.rn.f32x2 %0, %1, %2, %3;" : "=l"(acc) : "l"(a), "l"(b), "l"(acc));
}
__device__ __forceinline__ unsigned long long packf2(float lo, float hi) {
    unsigned long long r;
    asm("mov.b64 %0, {%1, %2};" : "=l"(r) : "f"(lo), "f"(hi));
    return r;
}
__device__ __forceinline__ void unpackf2(unsigned long long v, float& lo, float& hi) {
    asm("mov.b64 {%0, %1}, %2;" : "=f"(lo), "=f"(hi) : "l"(v));
}

// ---------------- Kernel A: massively parallel masked matvec ----------------
// warp w handles batch b = w/8, timesteps [chunk*125, chunk*125+125)
__global__ __launch_bounds__(128) void matvec_kernel(
    const float* __restrict__ x,     // [B, T, NI]
    const float* __restrict__ W1,    // [NR, NI]
    const float* __restrict__ mask,  // [NR, NI]
    const float* __restrict__ tau_n) // [NR]
{
    const int wib  = threadIdx.x >> 5;
    const int lane = threadIdx.x & 31;
    const int w    = blockIdx.x * 4 + wib;
    const int b    = w >> 3;
    const int t0   = (w & 7) * CHLEN;

    __shared__ __align__(16) float xbuf[4][2][48];

    const float beta   = 1.0f / (1.0f + expf(-tau_n[lane]));
    const float ombeta = 1.0f - beta;

    // masked weight row, pre-scaled by (1-beta), packed as f32x2 pairs
    unsigned long long wp[NI / 2];
    #pragma unroll
    for (int j = 0; j < NI / 2; ++j) {
        float a = W1[lane * NI + 2 * j]     * mask[lane * NI + 2 * j]     * ombeta;
        float c = W1[lane * NI + 2 * j + 1] * mask[lane * NI + 2 * j + 1] * ombeta;
        wp[j] = packf2(a, c);
    }

    const float* xp = x + ((size_t)b * TSTEPS + t0) * NI;
    float*       cp = g_cur + ((size_t)b * TSTEPS + t0) * NR + lane;

    xbuf[wib][0][lane] = xp[lane];
    if (lane < NI - 32) xbuf[wib][0][32 + lane] = xp[32 + lane];
    __syncwarp();

    #pragma unroll 2
    for (int i = 0; i < CHLEN; ++i) {
        const float* xn = xp + (size_t)((i + 1 < CHLEN) ? i + 1 : i) * NI;
        float nx0 = xn[lane];
        float nx1 = (lane < NI - 32) ? xn[32 + lane] : 0.0f;

        const unsigned long long* xrow =
            reinterpret_cast<const unsigned long long*>(&xbuf[wib][i & 1][0]);
        unsigned long long acc0 = 0ull, acc1 = 0ull;
        #pragma unroll
        for (int j = 0; j < 10; ++j) {
            fma2(acc0, wp[2 * j],     xrow[2 * j]);
            fma2(acc1, wp[2 * j + 1], xrow[2 * j + 1]);
        }
        float a0, a1, a2, a3;
        unpackf2(acc0, a0, a1);
        unpackf2(acc1, a2, a3);
        cp[(size_t)i * NR] = (a0 + a1) + (a2 + a3);

        xbuf[wib][(i + 1) & 1][lane] = nx0;
        if (lane < NI - 32) xbuf[wib][(i + 1) & 1][32 + lane] = nx1;
        __syncwarp();
    }
}

// ---------------- Kernel B: sequential recurrence, deep prefetch ------------
#define PD 10   // prefetch ring depth; TSTEPS % PD == 0

__global__ __launch_bounds__(32) void recur_kernel(
    const int*   __restrict__ target, // [B, T]
    const float* __restrict__ tau_m,  // [NH]
    const float* __restrict__ tau_n,  // [NR]
    const float* __restrict__ W2,     // [NO, NH]
    const float* __restrict__ b2,     // [NO]
    float*       __restrict__ out)
{
    const int b    = blockIdx.x;
    const int lane = threadIdx.x;
    const int h    = lane >> 1;
    const unsigned FULL = 0xffffffffu;

    const float beta    = 1.0f / (1.0f + expf(-tau_n[lane]));
    const float alpha   = 1.0f / (1.0f + expf(-tau_m[h]));
    const float omalpha = 1.0f - alpha;
    const float w2sel   = (lane & 1) ? W2[NH + h] : W2[h];
    const int   w2q      = __float2int_rn(w2sel * W2SCALE);
    const int   w2q_even = (lane & 1) ? 0 : w2q;
    const int   w2q_odd  = (lane & 1) ? w2q : 0;
    const float b20 = b2[0], b21 = b2[1];
    const float mybias = lane ? b21 : b20;

    const float* cp = g_cur + (size_t)b * TSTEPS * NR + lane;
    const int*   tp = target + (size_t)b * TSTEPS;
    float*       op = out + OUT_D2 + (size_t)b * TSTEPS * NO;

    float pc[PD];
    int   tq[PD];
    #pragma unroll
    for (int j = 0; j < PD; ++j) {
        pc[j] = cp[(size_t)j * NR];
        tq[j] = tp[j];
    }

    float d = 0.0f, mem = 0.0f, spkf = 0.0f;
    float lossAcc = 0.0f;
    int   corrAcc = 0;
    int   ph = -10;   // (t-10) mod 15 tracker; flag == ph > 5

    for (int tt = 0; tt < TSTEPS; tt += PD) {
        #pragma unroll
        for (int u = 0; u < PD; ++u) {
            const int t = tt + u;
            float pcur = pc[u];
            int   tgt  = tq[u];
            const int tn = t + PD;
            if (tn < TSTEPS) {            // refill ring slot
                pc[u] = cp[(size_t)tn * NR];
                tq[u] = tp[tn];
            }

            // dendrite (pre-scaled cur) + pair-sum + membrane + spike
            d = fmaf(beta, d, pcur);
            float l = d + __shfl_xor_sync(FULL, d, 1);
            mem = fmaf(alpha, mem - spkf, omalpha * l);
            bool spkb = mem > 1.0f;       // VTH = 1
            spkf = spkb ? 1.0f : 0.0f;

            // logits via warp-wide integer reductions
            int s0 = __reduce_add_sync(FULL, spkb ? w2q_even : 0);
            int s1 = __reduce_add_sync(FULL, spkb ? w2q_odd  : 0);
            float l0 = fmaf((float)s0, W2SCALE_INV, b20);
            float l1 = fmaf((float)s1, W2SCALE_INV, b21);

            if (lane < 2) {
                float myl = fmaf((float)(lane ? s1 : s0), W2SCALE_INV, mybias);
                op[2 * t + lane] = myl;
            }

            bool flag = ph > 5;
            ph = (ph == 14) ? 0 : ph + 1;
            if (flag) {
                float z  = l1 - l0;
                float p1 = 1.0f / (1.0f + __expf(-z));
                float p0 = 1.0f - p1;
                float lse = __logf(__expf(p0) + __expf(p1)); // double-softmax CE
                float ptgt = tgt ? p1 : p0;
                lossAcc += (lse - ptgt);
                corrAcc += (((z > 0.0f) ? 1 : 0) == tgt);
            }
        }
    }

    if (lane == 0) {
        atomicAdd(&out[OUT_LOSS], lossAcc * (1.0f / (float)BATCH));
        atomicAdd(&out[OUT_CORR], (float)corrAcc);
    }
}

extern "C" void kernel_launch(void* const* d_in, const int* in_sizes, int n_in,
                              void* d_out, int out_size) {
    const float* x      = (const float*)d_in[0];
    const int*   target = (const int*)  d_in[1];
    const float* W1     = (const float*)d_in[2];
    const float* tau_m  = (const float*)d_in[3];
    const float* tau_n  = (const float*)d_in[4];
    const float* mask   = (const float*)d_in[5];
    const float* W2     = (const float*)d_in[6];
    const float* b2     = (const float*)d_in[7];
    float* out = (float*)d_out;

    init_out<<<1, 32>>>(out);
    matvec_kernel<<<(BATCH * CHUNKS) / 4, 128>>>(x, W1, mask, tau_n);
    recur_kernel<<<BATCH, 32>>>(target, tau_m, tau_n, W2, b2, out);
}

// round 6
// speedup vs baseline: 1.7511x; 1.0027x over previous
#include <cuda_runtime.h>
#include <math.h>

#define BATCH 2048
#define TSTEPS 1000
#define NI 40
#define NH 16
#define NR 32
#define NO 2

#define CHUNKS 8
#define CHLEN (TSTEPS / CHUNKS)   // 125

#define OUT_LOSS 0
#define OUT_D2   1
#define OUT_CORR (1 + (size_t)BATCH * TSTEPS * NO)
#define OUT_TOT  (OUT_CORR + 1)

// 262 MB scratch: pre-scaled dendritic currents pc[b][t][r] = (1-beta_r)*cur
__device__ __align__(16) float g_cur[(size_t)BATCH * TSTEPS * NR];

__device__ __forceinline__ void fma2(unsigned long long& acc,
                                     unsigned long long a,
                                     unsigned long long b) {
    asm("fma.rn.f32x2 %0, %1, %2, %3;" : "=l"(acc) : "l"(a), "l"(b), "l"(acc));
}
__device__ __forceinline__ unsigned long long packf2(float lo, float hi) {
    unsigned long long r;
    asm("mov.b64 %0, {%1, %2};" : "=l"(r) : "f"(lo), "f"(hi));
    return r;
}
__device__ __forceinline__ void unpackf2(unsigned long long v, float& lo, float& hi) {
    asm("mov.b64 {%0, %1}, %2;" : "=f"(lo), "=f"(hi) : "l"(v));
}
__device__ __forceinline__ float sigm(float v) { return 1.0f / (1.0f + expf(-v)); }

// ---------------- Kernel A: massively parallel masked matvec ----------------
// warp w: batch b = w/8, timesteps [chunk*125, chunk*125+125)
__global__ __launch_bounds__(128) void matvec_kernel(
    const float* __restrict__ x,     // [B, T, NI]
    const float* __restrict__ W1,    // [NR, NI]
    const float* __restrict__ mask,  // [NR, NI]
    const float* __restrict__ tau_n, // [NR]
    float*       __restrict__ out)
{
    // fold scalar output init into this kernel (runs before recur_kernel)
    if (blockIdx.x == 0 && threadIdx.x == 0) {
        out[OUT_LOSS] = 0.0f;
        int c = 0;
        for (int t = 0; t < TSTEPS; ++t)
            if (t > 10 && ((t - 10) % 15) > 5) c++;
        out[OUT_CORR] = 0.0f;
        out[OUT_TOT] = (float)c * (float)BATCH;
    }

    const int wib  = threadIdx.x >> 5;
    const int lane = threadIdx.x & 31;
    const int w    = blockIdx.x * 4 + wib;
    const int b    = w >> 3;
    const int t0   = (w & 7) * CHLEN;

    __shared__ __align__(16) float xbuf[4][2][48];

    const float ombeta = 1.0f - sigm(tau_n[lane]);

    // masked weight row, pre-scaled by (1-beta), packed as f32x2 pairs
    unsigned long long wp[NI / 2];
    #pragma unroll
    for (int j = 0; j < NI / 2; ++j) {
        float a = W1[lane * NI + 2 * j]     * mask[lane * NI + 2 * j]     * ombeta;
        float c = W1[lane * NI + 2 * j + 1] * mask[lane * NI + 2 * j + 1] * ombeta;
        wp[j] = packf2(a, c);
    }

    const float* xp = x + ((size_t)b * TSTEPS + t0) * NI;
    float*       cp = g_cur + ((size_t)b * TSTEPS + t0) * NR + lane;

    xbuf[wib][0][lane] = xp[lane];
    if (lane < NI - 32) xbuf[wib][0][32 + lane] = xp[32 + lane];
    __syncwarp();

    #pragma unroll 2
    for (int i = 0; i < CHLEN; ++i) {
        const float* xn = xp + (size_t)((i + 1 < CHLEN) ? i + 1 : i) * NI;
        float nx0 = xn[lane];
        float nx1 = (lane < NI - 32) ? xn[32 + lane] : 0.0f;

        const ulonglong2* xrow =
            reinterpret_cast<const ulonglong2*>(&xbuf[wib][i & 1][0]);
        unsigned long long acc0 = 0ull, acc1 = 0ull;
        #pragma unroll
        for (int j = 0; j < 10; ++j) {
            ulonglong2 xv = xrow[j];            // LDS.128 broadcast
            fma2(acc0, wp[2 * j],     xv.x);
            fma2(acc1, wp[2 * j + 1], xv.y);
        }
        float a0, a1, a2, a3;
        unpackf2(acc0, a0, a1);
        unpackf2(acc1, a2, a3);
        cp[(size_t)i * NR] = (a0 + a1) + (a2 + a3);

        xbuf[wib][(i + 1) & 1][lane] = nx0;
        if (lane < NI - 32) xbuf[wib][(i + 1) & 1][32 + lane] = nx1;
        __syncwarp();
    }
}

// ---------------- Kernel B: recurrence, 8 lanes per batch -------------------
// lane gl (0..7) of each 8-lane group owns rows 4gl..4gl+3 = neurons 2gl,2gl+1
#define PD 10   // prefetch ring depth; TSTEPS % PD == 0

__global__ __launch_bounds__(128) void recur_kernel(
    const int*   __restrict__ target, // [B, T]
    const float* __restrict__ tau_m,  // [NH]
    const float* __restrict__ tau_n,  // [NR]
    const float* __restrict__ W2,     // [NO, NH]
    const float* __restrict__ b2,     // [NO]
    float*       __restrict__ out)
{
    const int lane = threadIdx.x & 31;
    const int warp = (blockIdx.x * 128 + threadIdx.x) >> 5;
    const int g    = lane >> 3;         // batch slot within warp (0..3)
    const int gl   = lane & 7;          // lane within group
    const int b    = warp * 4 + g;
    const unsigned FULL = 0xffffffffu;

    // per-lane constants: 4 rows, 2 neurons
    const float4 tn4 = *reinterpret_cast<const float4*>(tau_n + gl * 4);
    const float be0 = sigm(tn4.x), be1 = sigm(tn4.y);
    const float be2 = sigm(tn4.z), be3 = sigm(tn4.w);
    const float2 tm2 = *reinterpret_cast<const float2*>(tau_m + gl * 2);
    const float alA = sigm(tm2.x), omA = 1.0f - alA;
    const float alB = sigm(tm2.y), omB = 1.0f - alB;
    const int h0 = gl * 2;
    const float w20A = W2[h0],      w20B = W2[h0 + 1];       // -> l0
    const float w21A = W2[NH + h0], w21B = W2[NH + h0 + 1];  // -> l1
    const float b20 = b2[0], b21 = b2[1];

    const float4* cp = reinterpret_cast<const float4*>(g_cur)
                     + (size_t)b * TSTEPS * (NR / 4) + gl;
    const int*   tp = target + (size_t)b * TSTEPS;
    float*       op = out + OUT_D2 + (size_t)b * TSTEPS * NO;

    float4 pc[PD];
    int    tq[PD];
    #pragma unroll
    for (int j = 0; j < PD; ++j) {
        pc[j] = cp[(size_t)j * (NR / 4)];
        tq[j] = tp[j];
    }

    float d0 = 0.f, d1 = 0.f, d2 = 0.f, d3 = 0.f;
    float memA = 0.f, memB = 0.f, spkA = 0.f, spkB = 0.f;
    float lossAcc = 0.0f;
    int   corrAcc = 0;
    int   ph = -10;   // (t-10) mod 15 tracker; flag == ph > 5

    for (int tt = 0; tt < TSTEPS; tt += PD) {
        #pragma unroll
        for (int u = 0; u < PD; ++u) {
            const int t = tt + u;
            float4 v  = pc[u];
            int    tgt = tq[u];
            const int tn_ = t + PD;
            if (tn_ < TSTEPS) {                 // refill ring slot
                pc[u] = cp[(size_t)tn_ * (NR / 4)];
                tq[u] = tp[tn_];
            }

            // dendrites (pc pre-scaled by 1-beta); pair-sum is local now
            d0 = fmaf(be0, d0, v.x);
            d1 = fmaf(be1, d1, v.y);
            d2 = fmaf(be2, d2, v.z);
            d3 = fmaf(be3, d3, v.w);
            float lA = d0 + d1;
            float lB = d2 + d3;

            memA = fmaf(alA, memA - spkA, omA * lA);
            memB = fmaf(alB, memB - spkB, omB * lB);
            spkA = (memA > 1.0f) ? 1.0f : 0.0f;   // VTH = 1
            spkB = (memB > 1.0f) ? 1.0f : 0.0f;

            // logits: per-lane partials, 3-level xor tree within 8-lane group
            float p0 = fmaf(spkA, w20A, spkB * w20B);
            float p1 = fmaf(spkA, w21A, spkB * w21B);
            p0 += __shfl_xor_sync(FULL, p0, 1);
            p1 += __shfl_xor_sync(FULL, p1, 1);
            p0 += __shfl_xor_sync(FULL, p0, 2);
            p1 += __shfl_xor_sync(FULL, p1, 2);
            p0 += __shfl_xor_sync(FULL, p0, 4);
            p1 += __shfl_xor_sync(FULL, p1, 4);
            float l0 = p0 + b20;
            float l1 = p1 + b21;

            if (gl < 2) op[2 * t + gl] = gl ? l1 : l0;

            bool flag = ph > 5;
            ph = (ph == 14) ? 0 : ph + 1;
            if (flag) {
                float z  = l1 - l0;
                float q1 = 1.0f / (1.0f + __expf(-z));
                float q0 = 1.0f - q1;
                float lse = __logf(__expf(q0) + __expf(q1)); // double-softmax CE
                float ptgt = tgt ? q1 : q0;
                lossAcc += (lse - ptgt);
                corrAcc += (((z > 0.0f) ? 1 : 0) == tgt);
            }
        }
    }

    // all 8 lanes of a group hold identical loss/corr -> scale by 1/8 and
    // fold the 4 groups together, one atomic pair per warp
    lossAcc *= 0.125f;
    float corrF = (float)corrAcc * 0.125f;
    lossAcc += __shfl_xor_sync(FULL, lossAcc, 8);
    corrF   += __shfl_xor_sync(FULL, corrF, 8);
    lossAcc += __shfl_xor_sync(FULL, lossAcc, 16);
    corrF   += __shfl_xor_sync(FULL, corrF, 16);
    lossAcc += __shfl_xor_sync(FULL, lossAcc, 1);
    corrF   += __shfl_xor_sync(FULL, corrF, 1);
    lossAcc += __shfl_xor_sync(FULL, lossAcc, 2);
    corrF   += __shfl_xor_sync(FULL, corrF, 2);
    lossAcc += __shfl_xor_sync(FULL, lossAcc, 4);
    corrF   += __shfl_xor_sync(FULL, corrF, 4);
    if (lane == 0) {
        atomicAdd(&out[OUT_LOSS], lossAcc * (1.0f / (float)BATCH));
        atomicAdd(&out[OUT_CORR], corrF);
    }
}

extern "C" void kernel_launch(void* const* d_in, const int* in_sizes, int n_in,
                              void* d_out, int out_size) {
    const float* x      = (const float*)d_in[0];
    const int*   target = (const int*)  d_in[1];
    const float* W1     = (const float*)d_in[2];
    const float* tau_m  = (const float*)d_in[3];
    const float* tau_n  = (const float*)d_in[4];
    const float* mask   = (const float*)d_in[5];
    const float* W2     = (const float*)d_in[6];
    const float* b2     = (const float*)d_in[7];
    float* out = (float*)d_out;

    matvec_kernel<<<(BATCH * CHUNKS) / 4, 128>>>(x, W1, mask, tau_n, out);
    recur_kernel<<<(BATCH / 4) * 32 / 128, 128>>>(target, tau_m, tau_n, W2, b2, out);
}

// round 7
// speedup vs baseline: 2.2686x; 1.2955x over previous
#include <cuda_runtime.h>
#include <math.h>

#define BATCH 2048
#define TSTEPS 1000
#define NI 40
#define NH 16
#define NR 32
#define NO 2

#define CHUNKS 10
#define CHLEN (TSTEPS / CHUNKS)   // 100

#define OUT_LOSS 0
#define OUT_D2   1
#define OUT_CORR (1 + (size_t)BATCH * TSTEPS * NO)
#define OUT_TOT  (OUT_CORR + 1)

// 262 MB scratch: pre-scaled dendritic currents pc[b][t][r] = (1-beta_r)*cur
__device__ __align__(16) float g_cur[(size_t)BATCH * TSTEPS * NR];
// 4 MB scratch: packed spike ballots per recur-warp (4 batches) per step
__device__ __align__(16) uint2 g_ball[(size_t)(BATCH / 4) * TSTEPS];

__device__ __forceinline__ void fma2(unsigned long long& acc,
                                     unsigned long long a,
                                     unsigned long long b) {
    asm("fma.rn.f32x2 %0, %1, %2, %3;" : "=l"(acc) : "l"(a), "l"(b), "l"(acc));
}
__device__ __forceinline__ unsigned long long packf2(float lo, float hi) {
    unsigned long long r;
    asm("mov.b64 %0, {%1, %2};" : "=l"(r) : "f"(lo), "f"(hi));
    return r;
}
__device__ __forceinline__ void unpackf2(unsigned long long v, float& lo, float& hi) {
    asm("mov.b64 {%0, %1}, %2;" : "=f"(lo), "=f"(hi) : "l"(v));
}
__device__ __forceinline__ float sigm(float v) { return 1.0f / (1.0f + expf(-v)); }

// ---------------- Kernel A: massively parallel masked matvec ----------------
// warp w: batch b = w/CHUNKS, timesteps [c*CHLEN, (c+1)*CHLEN)
__global__ __launch_bounds__(256) void matvec_kernel(
    const float* __restrict__ x,     // [B, T, NI]
    const float* __restrict__ W1,    // [NR, NI]
    const float* __restrict__ mask,  // [NR, NI]
    const float* __restrict__ tau_n, // [NR]
    float*       __restrict__ out)
{
    if (blockIdx.x == 0 && threadIdx.x == 0) {
        out[OUT_LOSS] = 0.0f;
        int c = 0;
        for (int t = 0; t < TSTEPS; ++t)
            if (t > 10 && ((t - 10) % 15) > 5) c++;
        out[OUT_CORR] = 0.0f;
        out[OUT_TOT] = (float)c * (float)BATCH;
    }

    const int wib  = threadIdx.x >> 5;          // 0..7
    const int lane = threadIdx.x & 31;
    const int w    = blockIdx.x * 8 + wib;
    const int b    = w / CHUNKS;
    const int t0   = (w - b * CHUNKS) * CHLEN;

    // 4-deep x staging ring per warp
    __shared__ __align__(16) float xbuf[8][4][48];

    const float ombeta = 1.0f - sigm(tau_n[lane]);

    unsigned long long wp[NI / 2];               // (1-beta)-scaled masked row
    #pragma unroll
    for (int j = 0; j < NI / 2; ++j) {
        float a = W1[lane * NI + 2 * j]     * mask[lane * NI + 2 * j]     * ombeta;
        float c = W1[lane * NI + 2 * j + 1] * mask[lane * NI + 2 * j + 1] * ombeta;
        wp[j] = packf2(a, c);
    }

    const float* xp = x + ((size_t)b * TSTEPS + t0) * NI;
    float*       cp = g_cur + ((size_t)b * TSTEPS + t0) * NR + lane;

    // prologue: buffers 0,1 staged; x2,x3 held in pending regs
    xbuf[wib][0][lane] = xp[lane];
    if (lane < NI - 32) xbuf[wib][0][32 + lane] = xp[32 + lane];
    xbuf[wib][1][lane] = xp[NI + lane];
    if (lane < NI - 32) xbuf[wib][1][32 + lane] = xp[NI + 32 + lane];
    float pA0 = xp[2 * NI + lane];
    float pA1 = (lane < NI - 32) ? xp[2 * NI + 32 + lane] : 0.0f;
    float pB0 = xp[3 * NI + lane];
    float pB1 = (lane < NI - 32) ? xp[3 * NI + 32 + lane] : 0.0f;
    __syncwarp();

    #pragma unroll 2
    for (int i = 0; i < CHLEN; ++i) {
        const ulonglong2* xrow =
            reinterpret_cast<const ulonglong2*>(&xbuf[wib][i & 3][0]);
        unsigned long long acc0 = 0ull, acc1 = 0ull;
        #pragma unroll
        for (int j = 0; j < 10; ++j) {
            ulonglong2 xv = xrow[j];             // LDS.128 broadcast
            fma2(acc0, wp[2 * j],     xv.x);
            fma2(acc1, wp[2 * j + 1], xv.y);
        }
        float a0, a1, a2, a3;
        unpackf2(acc0, a0, a1);
        unpackf2(acc1, a2, a3);
        cp[(size_t)i * NR] = (a0 + a1) + (a2 + a3);

        // store x_{i+2} (LDG was issued 2 iters ago), shift pipeline, load x_{i+4}
        xbuf[wib][(i + 2) & 3][lane] = pA0;
        if (lane < NI - 32) xbuf[wib][(i + 2) & 3][32 + lane] = pA1;
        pA0 = pB0; pA1 = pB1;
        int ni = (i + 4 < CHLEN) ? i + 4 : CHLEN - 1;
        pB0 = xp[(size_t)ni * NI + lane];
        pB1 = (lane < NI - 32) ? xp[(size_t)ni * NI + 32 + lane] : 0.0f;
        __syncwarp();
    }
}

// ---------------- Kernel B: pure state recurrence ---------------------------
// lane gl (0..7) of each 8-lane group owns rows 4gl..4gl+3 = neurons 2gl,2gl+1
#define PD 10

__global__ __launch_bounds__(128) void recur_kernel(
    const float* __restrict__ tau_m,  // [NH]
    const float* __restrict__ tau_n)  // [NR]
{
    const int lane = threadIdx.x & 31;
    const int warp = (blockIdx.x * 128 + threadIdx.x) >> 5;
    const int g    = lane >> 3;
    const int gl   = lane & 7;
    const int b    = warp * 4 + g;
    const unsigned FULL = 0xffffffffu;

    const float4 tn4 = *reinterpret_cast<const float4*>(tau_n + gl * 4);
    const float be0 = sigm(tn4.x), be1 = sigm(tn4.y);
    const float be2 = sigm(tn4.z), be3 = sigm(tn4.w);
    const float2 tm2 = *reinterpret_cast<const float2*>(tau_m + gl * 2);
    const float alA = sigm(tm2.x), omA = 1.0f - alA;
    const float alB = sigm(tm2.y), omB = 1.0f - alB;

    const float4* cp = reinterpret_cast<const float4*>(g_cur)
                     + (size_t)b * TSTEPS * (NR / 4) + gl;
    uint2* bp = g_ball + (size_t)warp * TSTEPS;

    float4 pc[PD];
    #pragma unroll
    for (int j = 0; j < PD; ++j) pc[j] = cp[(size_t)j * (NR / 4)];

    float d0 = 0.f, d1 = 0.f, d2 = 0.f, d3 = 0.f;
    float memA = 0.f, memB = 0.f, spkA = 0.f, spkB = 0.f;

    for (int tt = 0; tt < TSTEPS; tt += PD) {
        #pragma unroll
        for (int u = 0; u < PD; ++u) {
            const int t = tt + u;
            float4 v = pc[u];
            const int tn_ = t + PD;
            if (tn_ < TSTEPS) pc[u] = cp[(size_t)tn_ * (NR / 4)];

            d0 = fmaf(be0, d0, v.x);
            d1 = fmaf(be1, d1, v.y);
            d2 = fmaf(be2, d2, v.z);
            d3 = fmaf(be3, d3, v.w);
            float lA = d0 + d1;
            float lB = d2 + d3;

            memA = fmaf(alA, memA - spkA, omA * lA);
            memB = fmaf(alB, memB - spkB, omB * lB);
            bool sA = memA > 1.0f;               // VTH = 1
            bool sB = memB > 1.0f;
            spkA = sA ? 1.0f : 0.0f;
            spkB = sB ? 1.0f : 0.0f;

            unsigned bA = __ballot_sync(FULL, sA);
            unsigned bB = __ballot_sync(FULL, sB);
            if (lane == 0) bp[t] = make_uint2(bA, bB);
        }
    }
}

// ---------------- Kernel C: parallel logits + CE/accuracy -------------------
#define CBLK 256

__global__ __launch_bounds__(CBLK) void logits_kernel(
    const int*   __restrict__ target, // [B, T] (row-major == linear b*T+t)
    const float* __restrict__ W2,     // [NO, NH]
    const float* __restrict__ b2,     // [NO]
    float*       __restrict__ out)
{
    __shared__ float LA0[256], LA1[256], LB0[256], LB1[256];
    __shared__ float redL[CBLK / 32], redC[CBLK / 32];

    // build byte-mask partial-sum LUTs: bit gl of bA-byte = neuron 2gl,
    // bit gl of bB-byte = neuron 2gl+1
    {
        int m = threadIdx.x;
        if (m < 256) {
            float a0 = 0.f, a1 = 0.f, c0 = 0.f, c1 = 0.f;
            #pragma unroll
            for (int gl = 0; gl < 8; ++gl) {
                if ((m >> gl) & 1) {
                    a0 += W2[2 * gl];
                    a1 += W2[NH + 2 * gl];
                    c0 += W2[2 * gl + 1];
                    c1 += W2[NH + 2 * gl + 1];
                }
            }
            LA0[m] = a0; LA1[m] = a1; LB0[m] = c0; LB1[m] = c1;
        }
    }
    __syncthreads();

    const float b20 = b2[0], b21 = b2[1];
    const int total = BATCH * TSTEPS;
    const int stride = gridDim.x * CBLK;

    float lossAcc = 0.0f;
    int   corrAcc = 0;

    for (int i = blockIdx.x * CBLK + threadIdx.x; i < total; i += stride) {
        int b = i / TSTEPS;
        int t = i - b * TSTEPS;
        uint2 ball = g_ball[(size_t)(b >> 2) * TSTEPS + t];
        int sh = (b & 3) * 8;
        int a = (ball.x >> sh) & 255;
        int c = (ball.y >> sh) & 255;
        float l0 = b20 + LA0[a] + LB0[c];
        float l1 = b21 + LA1[a] + LB1[c];
        out[OUT_D2 + 2 * (size_t)i]     = l0;
        out[OUT_D2 + 2 * (size_t)i + 1] = l1;

        bool flag = (t > 10) && (((t - 10) % 15) > 5);
        if (flag) {
            int tgt = target[i];
            float z  = l1 - l0;
            float p1 = 1.0f / (1.0f + __expf(-z));
            float p0 = 1.0f - p1;
            float lse = __logf(__expf(p0) + __expf(p1));  // double-softmax CE
            float ptgt = tgt ? p1 : p0;
            lossAcc += (lse - ptgt);
            corrAcc += (((z > 0.0f) ? 1 : 0) == tgt);
        }
    }

    // hierarchical reduction: warp shfl -> smem -> 2 atomics per block
    const unsigned FULL = 0xffffffffu;
    float corrF = (float)corrAcc;
    #pragma unroll
    for (int o = 16; o > 0; o >>= 1) {
        lossAcc += __shfl_xor_sync(FULL, lossAcc, o);
        corrF   += __shfl_xor_sync(FULL, corrF, o);
    }
    int wid = threadIdx.x >> 5;
    if ((threadIdx.x & 31) == 0) { redL[wid] = lossAcc; redC[wid] = corrF; }
    __syncthreads();
    if (threadIdx.x == 0) {
        float L = 0.f, C = 0.f;
        #pragma unroll
        for (int k = 0; k < CBLK / 32; ++k) { L += redL[k]; C += redC[k]; }
        atomicAdd(&out[OUT_LOSS], L * (1.0f / (float)BATCH));
        atomicAdd(&out[OUT_CORR], C);
    }
}

extern "C" void kernel_launch(void* const* d_in, const int* in_sizes, int n_in,
                              void* d_out, int out_size) {
    const float* x      = (const float*)d_in[0];
    const int*   target = (const int*)  d_in[1];
    const float* W1     = (const float*)d_in[2];
    const float* tau_m  = (const float*)d_in[3];
    const float* tau_n  = (const float*)d_in[4];
    const float* mask   = (const float*)d_in[5];
    const float* W2     = (const float*)d_in[6];
    const float* b2     = (const float*)d_in[7];
    float* out = (float*)d_out;

    matvec_kernel<<<(BATCH * CHUNKS) / 8, 256>>>(x, W1, mask, tau_n, out);
    recur_kernel<<<(BATCH / 4) * 32 / 128, 128>>>(tau_m, tau_n);
    logits_kernel<<<1024, CBLK>>>(target, W2, b2, out);
}

// round 8
// speedup vs baseline: 2.8673x; 1.2639x over previous
#include <cuda_runtime.h>
#include <math.h>

#define BATCH 2048
#define TSTEPS 1000
#define NI 40
#define NH 16
#define NR 32
#define NO 2

#define CHUNKS 10
#define CHLEN (TSTEPS / CHUNKS)   // 100

#define OUT_LOSS 0
#define OUT_D2   1
#define OUT_CORR (1 + (size_t)BATCH * TSTEPS * NO)
#define OUT_TOT  (OUT_CORR + 1)

// 262 MB scratch: pre-scaled dendritic currents pc[b][t][r] = (1-beta_r)*cur
__device__ __align__(16) float g_cur[(size_t)BATCH * TSTEPS * NR];
// 4 MB scratch: packed spike ballots per recur-warp (4 batches) per step
__device__ __align__(16) uint2 g_ball[(size_t)(BATCH / 4) * TSTEPS];

__device__ __forceinline__ void fma2(unsigned long long& acc,
                                     unsigned long long a,
                                     unsigned long long b) {
    asm("fma.rn.f32x2 %0, %1, %2, %3;" : "=l"(acc) : "l"(a), "l"(b), "l"(acc));
}
__device__ __forceinline__ unsigned long long packf2(float lo, float hi) {
    unsigned long long r;
    asm("mov.b64 %0, {%1, %2};" : "=l"(r) : "f"(lo), "f"(hi));
    return r;
}
__device__ __forceinline__ void unpackf2(unsigned long long v, float& lo, float& hi) {
    asm("mov.b64 {%0, %1}, %2;" : "=f"(lo), "=f"(hi) : "l"(v));
}
__device__ __forceinline__ float sigm(float v) { return 1.0f / (1.0f + expf(-v)); }

// ---------------- Kernel A: masked matvec, 2-way k-split --------------------
// warp w: batch b = w/CHUNKS, steps [c*CHLEN, (c+1)*CHLEN).
// lane l<16: rows 2l,2l+1 over k in [0,20); lane l+16: same rows, k in [20,40).
__global__ __launch_bounds__(128) void matvec_kernel(
    const float* __restrict__ x,     // [B, T, NI]
    const float* __restrict__ W1,    // [NR, NI]
    const float* __restrict__ mask,  // [NR, NI]
    const float* __restrict__ tau_n, // [NR]
    float*       __restrict__ out)
{
    if (blockIdx.x == 0 && threadIdx.x == 0) {
        out[OUT_LOSS] = 0.0f;
        int c = 0;
        for (int t = 0; t < TSTEPS; ++t)
            if (t > 10 && ((t - 10) % 15) > 5) c++;
        out[OUT_CORR] = 0.0f;
        out[OUT_TOT] = (float)c * (float)BATCH;
    }

    const int wib  = threadIdx.x >> 5;            // 0..3
    const int lane = threadIdx.x & 31;
    const int w    = blockIdx.x * 4 + wib;
    const int b    = w / CHUNKS;
    const int t0   = (w - b * CHUNKS) * CHLEN;
    const unsigned FULL = 0xffffffffu;

    __shared__ __align__(16) float xbuf[4][4][48]; // [warp][ring][step-row]

    const int rl   = lane & 15;
    const int row0 = 2 * rl;
    const int row1 = row0 + 1;
    const int koff = (lane >> 4) * 20;            // 0 or 20

    const float om0 = 1.0f - sigm(tau_n[row0]);
    const float om1 = 1.0f - sigm(tau_n[row1]);

    // 10 packed weight pairs per row for this lane's k-half
    unsigned long long wp0[10], wp1[10];
    #pragma unroll
    for (int j = 0; j < 10; ++j) {
        int k = koff + 2 * j;
        wp0[j] = packf2(W1[row0 * NI + k]     * mask[row0 * NI + k]     * om0,
                        W1[row0 * NI + k + 1] * mask[row0 * NI + k + 1] * om0);
        wp1[j] = packf2(W1[row1 * NI + k]     * mask[row1 * NI + k]     * om1,
                        W1[row1 * NI + k + 1] * mask[row1 * NI + k + 1] * om1);
    }

    const float* xp = x + ((size_t)b * TSTEPS + t0) * NI;
    float*       cp = g_cur + ((size_t)b * TSTEPS + t0) * NR + row0;

    // prologue: ring buffers 0,1 staged; steps 2,3 pending in registers
    xbuf[wib][0][lane] = xp[lane];
    if (lane < 8) xbuf[wib][0][32 + lane] = xp[32 + lane];
    xbuf[wib][1][lane] = xp[NI + lane];
    if (lane < 8) xbuf[wib][1][32 + lane] = xp[NI + 32 + lane];
    float pA0 = xp[2 * NI + lane];
    float pA1 = (lane < 8) ? xp[2 * NI + 32 + lane] : 0.0f;
    float pB0 = xp[3 * NI + lane];
    float pB1 = (lane < 8) ? xp[3 * NI + 32 + lane] : 0.0f;
    __syncwarp();

    const float* pf = xp + 4 * NI;
    // clamp target for the global last warp only; others may legally read
    // a few steps past their chunk (still inside x)
    const float* pmaxp = (w == BATCH * CHUNKS - 1)
                       ? xp + (size_t)(CHLEN - 1) * NI
                       : xp + (size_t)(CHLEN + 8) * NI;

    for (int i = 0; i < CHLEN; i += 4) {
        #pragma unroll
        for (int u = 0; u < 4; ++u) {
            // prefetch x for step i+u+4
            float nx0 = pf[lane];
            float nx1 = (lane < 8) ? pf[32 + lane] : 0.0f;
            pf += NI;
            if (pf > pmaxp) pf = pmaxp;

            // dot over this lane's k-half (static smem offsets)
            const ulonglong2* xr =
                reinterpret_cast<const ulonglong2*>(&xbuf[wib][u][koff]);
            unsigned long long acc0 = 0ull, acc1 = 0ull;
            #pragma unroll
            for (int j = 0; j < 5; ++j) {
                ulonglong2 v = xr[j];             // 2 distinct 16B regions/warp
                fma2(acc0, wp0[2 * j],     v.x);
                fma2(acc0, wp0[2 * j + 1], v.y);
                fma2(acc1, wp1[2 * j],     v.x);
                fma2(acc1, wp1[2 * j + 1], v.y);
            }
            float a0, a1, b0, b1;
            unpackf2(acc0, a0, a1);
            unpackf2(acc1, b0, b1);
            float h0 = a0 + a1;
            float h1 = b0 + b1;
            // combine the two k-halves (lanes l <-> l+16)
            h0 += __shfl_xor_sync(FULL, h0, 16);
            h1 += __shfl_xor_sync(FULL, h1, 16);

            if (lane < 16) *reinterpret_cast<float2*>(cp) = make_float2(h0, h1);
            cp += NR;

            // stage pending step i+u+2, shift pipeline
            xbuf[wib][(u + 2) & 3][lane] = pA0;
            if (lane < 8) xbuf[wib][(u + 2) & 3][32 + lane] = pA1;
            pA0 = pB0; pA1 = pB1;
            pB0 = nx0; pB1 = nx1;
            __syncwarp();
        }
    }
}

// ---------------- Kernel B: pure state recurrence ---------------------------
// lane gl (0..7) of each 8-lane group owns rows 4gl..4gl+3 = neurons 2gl,2gl+1
#define PD 20

__global__ __launch_bounds__(128) void recur_kernel(
    const float* __restrict__ tau_m,  // [NH]
    const float* __restrict__ tau_n)  // [NR]
{
    const int lane = threadIdx.x & 31;
    const int warp = (blockIdx.x * 128 + threadIdx.x) >> 5;
    const int g    = lane >> 3;
    const int gl   = lane & 7;
    const int b    = warp * 4 + g;
    const unsigned FULL = 0xffffffffu;

    const float4 tn4 = *reinterpret_cast<const float4*>(tau_n + gl * 4);
    const float be0 = sigm(tn4.x), be1 = sigm(tn4.y);
    const float be2 = sigm(tn4.z), be3 = sigm(tn4.w);
    const float2 tm2 = *reinterpret_cast<const float2*>(tau_m + gl * 2);
    const float alA = sigm(tm2.x), omA = 1.0f - alA;
    const float alB = sigm(tm2.y), omB = 1.0f - alB;

    const float4* cp = reinterpret_cast<const float4*>(g_cur)
                     + (size_t)b * TSTEPS * (NR / 4) + gl;
    uint2* bp = g_ball + (size_t)warp * TSTEPS;

    float4 pc[PD];
    #pragma unroll
    for (int j = 0; j < PD; ++j) pc[j] = cp[(size_t)j * (NR / 4)];

    float d0 = 0.f, d1 = 0.f, d2 = 0.f, d3 = 0.f;
    float memA = 0.f, memB = 0.f, spkA = 0.f, spkB = 0.f;

    for (int tt = 0; tt < TSTEPS; tt += PD) {
        #pragma unroll
        for (int u = 0; u < PD; ++u) {
            const int t = tt + u;
            float4 v = pc[u];
            const int tn_ = t + PD;
            if (tn_ < TSTEPS) pc[u] = cp[(size_t)tn_ * (NR / 4)];

            d0 = fmaf(be0, d0, v.x);
            d1 = fmaf(be1, d1, v.y);
            d2 = fmaf(be2, d2, v.z);
            d3 = fmaf(be3, d3, v.w);
            float lA = d0 + d1;
            float lB = d2 + d3;

            memA = fmaf(alA, memA - spkA, omA * lA);
            memB = fmaf(alB, memB - spkB, omB * lB);
            bool sA = memA > 1.0f;               // VTH = 1
            bool sB = memB > 1.0f;
            spkA = sA ? 1.0f : 0.0f;
            spkB = sB ? 1.0f : 0.0f;

            unsigned bA = __ballot_sync(FULL, sA);
            unsigned bB = __ballot_sync(FULL, sB);
            if (lane == 0) bp[t] = make_uint2(bA, bB);
        }
    }
}

// ---------------- Kernel C: parallel logits + CE/accuracy -------------------
#define CBLK 256

__global__ __launch_bounds__(CBLK) void logits_kernel(
    const int*   __restrict__ target, // [B, T]
    const float* __restrict__ W2,     // [NO, NH]
    const float* __restrict__ b2,     // [NO]
    float*       __restrict__ out)
{
    __shared__ float LA0[256], LA1[256], LB0[256], LB1[256];
    __shared__ float redL[CBLK / 32], redC[CBLK / 32];

    {
        int m = threadIdx.x;
        if (m < 256) {
            float a0 = 0.f, a1 = 0.f, c0 = 0.f, c1 = 0.f;
            #pragma unroll
            for (int gl = 0; gl < 8; ++gl) {
                if ((m >> gl) & 1) {
                    a0 += W2[2 * gl];
                    a1 += W2[NH + 2 * gl];
                    c0 += W2[2 * gl + 1];
                    c1 += W2[NH + 2 * gl + 1];
                }
            }
            LA0[m] = a0; LA1[m] = a1; LB0[m] = c0; LB1[m] = c1;
        }
    }
    __syncthreads();

    const float b20 = b2[0], b21 = b2[1];
    const int total = BATCH * TSTEPS;
    const int stride = gridDim.x * CBLK;

    float lossAcc = 0.0f;
    int   corrAcc = 0;

    for (int i = blockIdx.x * CBLK + threadIdx.x; i < total; i += stride) {
        int b = i / TSTEPS;
        int t = i - b * TSTEPS;
        uint2 ball = g_ball[(size_t)(b >> 2) * TSTEPS + t];
        int sh = (b & 3) * 8;
        int a = (ball.x >> sh) & 255;
        int c = (ball.y >> sh) & 255;
        float l0 = b20 + LA0[a] + LB0[c];
        float l1 = b21 + LA1[a] + LB1[c];
        out[OUT_D2 + 2 * (size_t)i]     = l0;
        out[OUT_D2 + 2 * (size_t)i + 1] = l1;

        bool flag = (t > 10) && (((t - 10) % 15) > 5);
        if (flag) {
            int tgt = target[i];
            float z  = l1 - l0;
            float p1 = 1.0f / (1.0f + __expf(-z));
            float p0 = 1.0f - p1;
            float lse = __logf(__expf(p0) + __expf(p1));  // double-softmax CE
            float ptgt = tgt ? p1 : p0;
            lossAcc += (lse - ptgt);
            corrAcc += (((z > 0.0f) ? 1 : 0) == tgt);
        }
    }

    const unsigned FULL = 0xffffffffu;
    float corrF = (float)corrAcc;
    #pragma unroll
    for (int o = 16; o > 0; o >>= 1) {
        lossAcc += __shfl_xor_sync(FULL, lossAcc, o);
        corrF   += __shfl_xor_sync(FULL, corrF, o);
    }
    int wid = threadIdx.x >> 5;
    if ((threadIdx.x & 31) == 0) { redL[wid] = lossAcc; redC[wid] = corrF; }
    __syncthreads();
    if (threadIdx.x == 0) {
        float L = 0.f, C = 0.f;
        #pragma unroll
        for (int k = 0; k < CBLK / 32; ++k) { L += redL[k]; C += redC[k]; }
        atomicAdd(&out[OUT_LOSS], L * (1.0f / (float)BATCH));
        atomicAdd(&out[OUT_CORR], C);
    }
}

extern "C" void kernel_launch(void* const* d_in, const int* in_sizes, int n_in,
                              void* d_out, int out_size) {
    const float* x      = (const float*)d_in[0];
    const int*   target = (const int*)  d_in[1];
    const float* W1     = (const float*)d_in[2];
    const float* tau_m  = (const float*)d_in[3];
    const float* tau_n  = (const float*)d_in[4];
    const float* mask   = (const float*)d_in[5];
    const float* W2     = (const float*)d_in[6];
    const float* b2     = (const float*)d_in[7];
    float* out = (float*)d_out;

    matvec_kernel<<<(BATCH * CHUNKS) / 4, 128>>>(x, W1, mask, tau_n, out);
    recur_kernel<<<(BATCH / 4) * 32 / 128, 128>>>(tau_m, tau_n);
    logits_kernel<<<1024, CBLK>>>(target, W2, b2, out);
}